// round 16
// baseline (speedup 1.0000x reference)
#include <cuda_runtime.h>
#include <cuda_bf16.h>
#include <stdint.h>
#include <cstdint>
#include <math.h>

#define BB 8
#define NN 1024
#define FF 512
#define HH 4
#define DD 128
#define ROWS (BB*NN)            // 8192
#define BH   (BB*HH)            // 32
#define TILE 32
#define TSH  5
#define NT   (NN/TILE)          // 32
#define LN_EPS 1e-5f
#define FLOATMAX 3.402823466e+38f

// GEMM staging: K chunks of 32 elems (64 B/row), tile = 128 rows x 64 B = 8 KB
#define KC    32
#define NSTG  (FF/KC)           // 16
#define TILEB 8192
#define STGB  (4*TILEB)         // 32 KB per stage (Ahi,Alo,Bhi,Blo)
#define NBUF  3
#define SMEM_GEMM (1024 + NBUF*STGB)   // 99328 -> 2 CTAs/SM

// ---------------- scratch (static device globals; no allocs allowed) ----------
__device__ float g_h[(size_t)ROWS*FF];                 // 16 MB: h = x @ W
// tiled+swizzled bf16: tile (rb*16+kc) is 8KB contiguous;
// byte(r, cu16) at r*64 + ((cu ^ ((r>>1)&3))*16)
__device__ __align__(128) __nv_bfloat16 g_ahi[(size_t)ROWS*FF];
__device__ __align__(128) __nv_bfloat16 g_alo[(size_t)ROWS*FF];
__device__ __align__(128) __nv_bfloat16 g_bhi[FF*FF];
__device__ __align__(128) __nv_bfloat16 g_blo[FF*FF];
__device__ float g_esrc[ROWS*HH];
__device__ float g_edst[ROWS*HH];
__device__ float g_key [BH*NN];
__device__ int   g_sidx[BH*NN];
__device__ int   g_nvalid[BB];
__device__ float g_p1[(size_t)BH*NN*DD];               // tile-LOCAL inclusive prefixes
__device__ float g_p2[(size_t)BH*NN*DD];
__device__ float g_t1[BH*NT*DD];
__device__ float g_t2[BH*NT*DD];
__device__ float g_off1[BH*(NT+1)*DD];
__device__ float g_off2[BH*(NT+1)*DD];
__device__ float g_hp[BH*NT*DD];
__device__ float g_s1[BH*(NN+1)];
__device__ float g_s2[BH*(NN+1)];
__device__ float g_hmean[BH*DD];

// ---------------- helpers -------------------------------------------------------
__device__ __forceinline__ uint32_t smem_u32(const void* p) {
    uint32_t a;
    asm("{ .reg .u64 t; cvta.to.shared.u64 t, %1; cvt.u32.u64 %0, t; }"
        : "=r"(a) : "l"(p));
    return a;
}
__device__ __forceinline__ void ldmx4(uint32_t* r, uint32_t addr) {
    asm volatile("ldmatrix.sync.aligned.m8n8.x4.shared.b16 {%0,%1,%2,%3}, [%4];"
                 : "=r"(r[0]), "=r"(r[1]), "=r"(r[2]), "=r"(r[3]) : "r"(addr));
}
__device__ __forceinline__ void ldmx2(uint32_t* r, uint32_t addr) {
    asm volatile("ldmatrix.sync.aligned.m8n8.x2.shared.b16 {%0,%1}, [%2];"
                 : "=r"(r[0]), "=r"(r[1]) : "r"(addr));
}
__device__ __forceinline__ void mma16816(float* c, const uint32_t* a, const uint32_t* b) {
    asm volatile(
        "mma.sync.aligned.m16n8k16.row.col.f32.bf16.bf16.f32 "
        "{%0,%1,%2,%3}, {%4,%5,%6,%7}, {%8,%9}, {%0,%1,%2,%3};"
        : "+f"(c[0]), "+f"(c[1]), "+f"(c[2]), "+f"(c[3])
        : "r"(a[0]), "r"(a[1]), "r"(a[2]), "r"(a[3]), "r"(b[0]), "r"(b[1]));
}
__device__ __forceinline__ void mbar_wait(uint32_t mbar, uint32_t parity) {
    asm volatile(
        "{\n\t.reg .pred P;\n"
        "W1_%=:\n\t"
        "mbarrier.try_wait.parity.acquire.cta.shared::cta.b64 P, [%0], %1, 0x989680;\n\t"
        "@P bra.uni W2_%=;\n\t"
        "bra.uni W1_%=;\n"
        "W2_%=:\n\t}"
        :: "r"(mbar), "r"(parity) : "memory");
}
__device__ __forceinline__ void bulk_g2s(uint32_t dst, const void* src,
                                         uint32_t bytes, uint32_t mbar) {
    asm volatile(
        "cp.async.bulk.shared::cluster.global.mbarrier::complete_tx::bytes "
        "[%0], [%1], %2, [%3];"
        :: "r"(dst), "l"(src), "r"(bytes), "r"(mbar) : "memory");
}
// swizzled in-tile byte offset for row r, 16B-unit cu (0..3)
#define TSWZ(r, cu) ((uint32_t)((r) * 64 + (((cu) ^ (((r) >> 1) & 3)) << 4)))

// ---------------- kernel 0a: split x -> tiled/swizzled bf16 hi/lo --------------
__global__ __launch_bounds__(256)
void k_convA(const float* __restrict__ x)
{
    size_t i = ((size_t)blockIdx.x * 256 + threadIdx.x) * 8;
    int row = (int)(i >> 9);
    int k   = (int)(i & 511);
    int rb = row >> 7, r = row & 127;
    int kcI = k >> 5, cu = (k >> 3) & 3;
    size_t off = ((size_t)(rb * 16 + kcI) << 13) + TSWZ(r, cu);

    float4 a = *reinterpret_cast<const float4*>(x + i);
    float4 b = *reinterpret_cast<const float4*>(x + i + 4);
    float v[8] = {a.x, a.y, a.z, a.w, b.x, b.y, b.z, b.w};
    union { __nv_bfloat16 h[8]; uint4 u; } hi, lo;
#pragma unroll
    for (int u = 0; u < 8; u++) {
        __nv_bfloat16 hv = __float2bfloat16(v[u]);
        hi.h[u] = hv;
        lo.h[u] = __float2bfloat16(v[u] - __bfloat162float(hv));
    }
    *reinterpret_cast<uint4*>(reinterpret_cast<char*>(g_ahi) + off) = hi.u;
    *reinterpret_cast<uint4*>(reinterpret_cast<char*>(g_alo) + off) = lo.u;
}

// ---------------- kernel 0b: split+transpose W -> tiled/swizzled [N][K] --------
__global__ __launch_bounds__(256)
void k_convB(const float* __restrict__ W)
{
    __shared__ float ts[64][65];
    int tid = threadIdx.x;
    int kt = blockIdx.x * 64, nt = blockIdx.y * 64;
#pragma unroll
    for (int p = 0; p < 16; p++) {
        int idx = tid + p * 256;
        int kl = idx >> 6, nl = idx & 63;
        ts[nl][kl] = W[(size_t)(kt + kl) * FF + nt + nl];
    }
    __syncthreads();
#pragma unroll
    for (int v = 0; v < 2; v++) {
        int u  = tid & 7;                   // 16B unit within 64 k-elems
        int nl = (tid >> 3) + v * 32;
        union { __nv_bfloat16 h[8]; uint4 q; } hi, lo;
#pragma unroll
        for (int w = 0; w < 8; w++) {
            float val = ts[nl][u * 8 + w];
            __nv_bfloat16 hv = __float2bfloat16(val);
            hi.h[w] = hv;
            lo.h[w] = __float2bfloat16(val - __bfloat162float(hv));
        }
        int n = nt + nl;
        int cb = n >> 7, r = n & 127;
        int kcI = (kt >> 5) + (u >> 2), cu = u & 3;
        size_t off = ((size_t)(cb * 16 + kcI) << 13) + TSWZ(r, cu);
        *reinterpret_cast<uint4*>(reinterpret_cast<char*>(g_bhi) + off) = hi.q;
        *reinterpret_cast<uint4*>(reinterpret_cast<char*>(g_blo) + off) = lo.q;
    }
}

// ---------------- kernel 0c: nvalid counts (also pads launch order) ------------
__global__ __launch_bounds__(1024)
void k_nv(const int* __restrict__ mask)
{
    int b = blockIdx.x;
    int cnt = __syncthreads_count(mask[b * NN + threadIdx.x] != 0);
    if (threadIdx.x == 0) g_nvalid[b] = cnt;
}

// ---------------- kernel 1: bulk-copy + mma.sync bf16x3 GEMM + fused eproj -----
// grid (4, 64): CTA = 128 rows x 128 cols (one head). 2 CTAs/SM.
__global__ __launch_bounds__(256, 2)
void k_gemm_mma(const float* __restrict__ a_src, const float* __restrict__ a_dst)
{
    extern __shared__ __align__(128) char smc[];
    const uint32_t sb = smem_u32(smc);
    const int tid = threadIdx.x, wid = tid >> 5, lane = tid & 31;
    const int wm = wid & 1, wn = wid >> 1;
    const int rowBlock = blockIdx.y, head = blockIdx.x;
    const int rowBase = rowBlock * 128;

    const uint32_t mb  = sb;
    const uint32_t stg = sb + 1024;

    if (tid == 0) {
#pragma unroll
        for (int i = 0; i < NBUF; i++)
            asm volatile("mbarrier.init.shared.b64 [%0], %1;"
                         :: "r"(mb + 8u * i), "r"(1u) : "memory");
    }
    __syncthreads();

    const char* gA0 = reinterpret_cast<const char*>(g_ahi) + (size_t)rowBlock * NSTG * TILEB;
    const char* gA1 = reinterpret_cast<const char*>(g_alo) + (size_t)rowBlock * NSTG * TILEB;
    const char* gB0 = reinterpret_cast<const char*>(g_bhi) + (size_t)head * NSTG * TILEB;
    const char* gB1 = reinterpret_cast<const char*>(g_blo) + (size_t)head * NSTG * TILEB;

    auto issue = [&](int s) {
        int buf = s % NBUF;
        uint32_t mbar = mb + 8u * buf;
        uint32_t d = stg + (uint32_t)buf * STGB;
        asm volatile("mbarrier.arrive.expect_tx.shared.b64 _, [%0], %1;"
                     :: "r"(mbar), "r"((uint32_t)STGB) : "memory");
        bulk_g2s(d + 0 * TILEB, gA0 + (size_t)s * TILEB, TILEB, mbar);
        bulk_g2s(d + 1 * TILEB, gA1 + (size_t)s * TILEB, TILEB, mbar);
        bulk_g2s(d + 2 * TILEB, gB0 + (size_t)s * TILEB, TILEB, mbar);
        bulk_g2s(d + 3 * TILEB, gB1 + (size_t)s * TILEB, TILEB, mbar);
    };
    if (tid == 0) { issue(0); issue(1); issue(2); }

    float acc[4][4][4];
#pragma unroll
    for (int i = 0; i < 4; i++)
#pragma unroll
        for (int j = 0; j < 4; j++)
#pragma unroll
            for (int c = 0; c < 4; c++) acc[i][j][c] = 0.f;

    for (int s = 0; s < NSTG; s++) {
        int buf = s % NBUF;
        mbar_wait(mb + 8u * buf, (uint32_t)((s / NBUF) & 1));
        uint32_t base = stg + (uint32_t)buf * STGB;
#pragma unroll
        for (int ks = 0; ks < 2; ks++) {
            uint32_t ah[4][4], al[4][4], bh[4][2], bl[4][2];
#pragma unroll
            for (int i = 0; i < 4; i++) {
                int r = wm * 64 + i * 16 + (lane & 15);
                int c = ks * 2 + (lane >> 4);
                uint32_t ad = base + TSWZ(r, c);
                ldmx4(ah[i], ad);
                ldmx4(al[i], ad + TILEB);
            }
#pragma unroll
            for (int j = 0; j < 4; j++) {
                int r = wn * 32 + j * 8 + (lane & 7);
                int c = ks * 2 + ((lane >> 3) & 1);
                uint32_t bd = base + 2 * TILEB + TSWZ(r, c);
                ldmx2(bh[j], bd);
                ldmx2(bl[j], bd + TILEB);
            }
#pragma unroll
            for (int i = 0; i < 4; i++)
#pragma unroll
                for (int j = 0; j < 4; j++) {
                    mma16816(acc[i][j], ah[i], bh[j]);
                    mma16816(acc[i][j], ah[i], bl[j]);
                    mma16816(acc[i][j], al[i], bh[j]);
                }
        }
        __syncthreads();
        if (tid == 0 && s + NBUF < NSTG) issue(s + NBUF);
    }

    // ---- epilogue 1: fragments -> g_h --------------------------------------
    const int r0 = rowBase + wm * 64, c0 = head * 128 + wn * 32;
#pragma unroll
    for (int i = 0; i < 4; i++)
#pragma unroll
        for (int j = 0; j < 4; j++) {
            int rr = r0 + i * 16 + (lane >> 2);
            int cc = c0 + j * 8 + (lane & 3) * 2;
            float2 v0 = make_float2(acc[i][j][0], acc[i][j][1]);
            float2 v1 = make_float2(acc[i][j][2], acc[i][j][3]);
            *reinterpret_cast<float2*>(&g_h[(size_t)rr * FF + cc]) = v0;
            *reinterpret_cast<float2*>(&g_h[(size_t)(rr + 8) * FF + cc]) = v1;
        }

    // ---- epilogue 2: fused e_src / e_dst -----------------------------------
    float as_[4][2], ad_[4][2];
#pragma unroll
    for (int j = 0; j < 4; j++) {
        int cl = wn * 32 + j * 8 + (lane & 3) * 2;
        as_[j][0] = a_src[head * DD + cl];
        as_[j][1] = a_src[head * DD + cl + 1];
        ad_[j][0] = a_dst[head * DD + cl];
        ad_[j][1] = a_dst[head * DD + cl + 1];
    }
    float es[8], ed[8];
#pragma unroll
    for (int i = 0; i < 4; i++)
#pragma unroll
        for (int sub = 0; sub < 2; sub++) {
            float s_ = 0.f, d_ = 0.f;
#pragma unroll
            for (int j = 0; j < 4; j++) {
                s_ += acc[i][j][sub * 2] * as_[j][0] + acc[i][j][sub * 2 + 1] * as_[j][1];
                d_ += acc[i][j][sub * 2] * ad_[j][0] + acc[i][j][sub * 2 + 1] * ad_[j][1];
            }
            es[i * 2 + sub] = s_;
            ed[i * 2 + sub] = d_;
        }
#pragma unroll
    for (int o = 1; o <= 2; o <<= 1)
#pragma unroll
        for (int t = 0; t < 8; t++) {
            es[t] += __shfl_xor_sync(0xffffffffu, es[t], o);
            ed[t] += __shfl_xor_sync(0xffffffffu, ed[t], o);
        }
    float* e_s = reinterpret_cast<float*>(smc + 1024);        // [128][4]
    float* e_d = reinterpret_cast<float*>(smc + 1024 + 2048); // [128][4]
    __syncthreads();
    if ((lane & 3) == 0) {
#pragma unroll
        for (int i = 0; i < 4; i++)
#pragma unroll
            for (int sub = 0; sub < 2; sub++) {
                int r = wm * 64 + i * 16 + sub * 8 + (lane >> 2);
                e_s[r * 4 + wn] = es[i * 2 + sub];
                e_d[r * 4 + wn] = ed[i * 2 + sub];
            }
    }
    __syncthreads();
    if (tid < 128) {
        float s_ = e_s[tid * 4 + 0] + e_s[tid * 4 + 1] + e_s[tid * 4 + 2] + e_s[tid * 4 + 3];
        float d_ = e_d[tid * 4 + 0] + e_d[tid * 4 + 1] + e_d[tid * 4 + 2] + e_d[tid * 4 + 3];
        g_esrc[(rowBase + tid) * 4 + head] = s_;
        g_edst[(rowBase + tid) * 4 + head] = d_;
    }
}

// ---------------- kernel 3: per (b,h) hybrid bitonic sort ----------------------
__global__ __launch_bounds__(1024)
void k_sort(const int* __restrict__ mask)
{
    int bh = blockIdx.x;
    int b  = bh >> 2, hh = bh & 3;
    int tid = threadIdx.x;
    __shared__ float skey[NN];
    __shared__ int   ssid[NN];

    int m = mask[b * NN + tid];
    float e = g_edst[(b * NN + tid) * 4 + hh];
    float kv = (m != 0) ? e : FLOATMAX;
    int   iv = tid;

    // stages k = 2..32: fully intra-warp
#pragma unroll
    for (int k = 2; k <= 32; k <<= 1) {
#pragma unroll
        for (int j = k >> 1; j > 0; j >>= 1) {
            bool up   = ((tid & k) == 0);
            bool lowr = ((tid & j) == 0);
            float ok = __shfl_xor_sync(0xffffffffu, kv, j);
            int   oi = __shfl_xor_sync(0xffffffffu, iv, j);
            bool take = up ? (lowr ? (ok < kv) : (ok > kv))
                           : (lowr ? (ok > kv) : (ok < kv));
            if (take) { kv = ok; iv = oi; }
        }
    }

    // stages k = 64..1024: j>=32 in smem, then j=16..1 in registers
#pragma unroll
    for (int k = 64; k <= NN; k <<= 1) {
        skey[tid] = kv; ssid[tid] = iv;
        __syncthreads();
#pragma unroll
        for (int j = k >> 1; j >= 32; j >>= 1) {
            int ixj = tid ^ j;
            if (ixj > tid) {
                bool up = ((tid & k) == 0);
                float ka = skey[tid], kb = skey[ixj];
                if ((ka > kb) == up) {
                    skey[tid] = kb; skey[ixj] = ka;
                    int ia = ssid[tid]; ssid[tid] = ssid[ixj]; ssid[ixj] = ia;
                }
            }
            __syncthreads();
        }
        kv = skey[tid]; iv = ssid[tid];
        bool up = ((tid & k) == 0);
#pragma unroll
        for (int j = 16; j > 0; j >>= 1) {
            bool lowr = ((tid & j) == 0);
            float ok = __shfl_xor_sync(0xffffffffu, kv, j);
            int   oi = __shfl_xor_sync(0xffffffffu, iv, j);
            bool take = up ? (lowr ? (ok < kv) : (ok > kv))
                           : (lowr ? (ok > kv) : (ok < kv));
            if (take) { kv = ok; iv = oi; }
        }
    }

    g_key [bh * NN + tid] = kv;
    g_sidx[bh * NN + tid] = iv;
}

// ---------------- kernel 4a: tile-local prefix scans + hmean partials ---------
__global__ __launch_bounds__(DD)
void k_scanA()
{
    int t  = blockIdx.x;
    int bh = blockIdx.y;
    int b = bh >> 2, hh = bh & 3;
    int d = threadIdx.x;

    __shared__ int   sj [TILE];
    __shared__ float sw1[TILE];
    __shared__ float sw2[TILE];

    int nv = g_nvalid[b];
    if (d < TILE) {
        int k = t * TILE + d;
        sj[d] = g_sidx[bh * NN + k];
        float e = g_key[bh * NN + k];
        bool v = (k < nv);
        sw1[d] = v ? __expf(0.2f * e) : 0.f;
        sw2[d] = v ? __expf(e) : 0.f;
    }
    __syncthreads();

    const float* hb = g_h + ((size_t)b << 10) * FF + hh * DD + d;
    float* P1 = g_p1 + ((size_t)bh * NN + t * TILE) * DD + d;
    float* P2 = g_p2 + ((size_t)bh * NN + t * TILE) * DD + d;

    float acc1 = 0.f, acc2 = 0.f;
    float hv[8];
#pragma unroll
    for (int u = 0; u < 8; u++) hv[u] = hb[(size_t)sj[u] * FF];
#pragma unroll
    for (int m0 = 0; m0 < TILE; m0 += 8) {
        float cur[8];
#pragma unroll
        for (int u = 0; u < 8; u++) cur[u] = hv[u];
        if (m0 + 8 < TILE) {
#pragma unroll
            for (int u = 0; u < 8; u++) hv[u] = hb[(size_t)sj[m0 + 8 + u] * FF];
        }
#pragma unroll
        for (int u = 0; u < 8; u++) {
            int m = m0 + u;
            acc1 = fmaf(sw1[m], cur[u], acc1);
            acc2 = fmaf(sw2[m], cur[u], acc2);
            P1[(size_t)m * DD] = acc1;
            P2[(size_t)m * DD] = acc2;
        }
    }
    g_t1[(bh * NT + t) * DD + d] = acc1;
    g_t2[(bh * NT + t) * DD + d] = acc2;

    if (d == 0) {
        float s1 = 0.f, s2 = 0.f;
        int base = bh * (NN + 1) + t * TILE;
#pragma unroll 8
        for (int m = 0; m < TILE; m++) {
            s1 += sw1[m]; s2 += sw2[m];
            g_s1[base + m + 1] = s1;
            g_s2[base + m + 1] = s2;
        }
    }

    float m0a = 0.f, m1a = 0.f, m2a = 0.f, m3a = 0.f;
    const float* hj = g_h + (((size_t)b << 10) + t * TILE) * FF + hh * DD + d;
#pragma unroll 8
    for (int j = 0; j < TILE; j += 4) {
        m0a += hj[(size_t)(j + 0) * FF];
        m1a += hj[(size_t)(j + 1) * FF];
        m2a += hj[(size_t)(j + 2) * FF];
        m3a += hj[(size_t)(j + 3) * FF];
    }
    g_hp[(bh * NT + t) * DD + d] = (m0a + m1a) + (m2a + m3a);
}

// ---------------- kernel 4b: tile offsets + scalar fixup + hmean --------------
__global__ __launch_bounds__(DD)
void k_scanB()
{
    int bh = blockIdx.x;
    int d  = threadIdx.x;

    float o1 = 0.f, o2 = 0.f, hm = 0.f;
#pragma unroll
    for (int t = 0; t < NT; t++) {
        g_off1[(bh * (NT + 1) + t) * DD + d] = o1;
        g_off2[(bh * (NT + 1) + t) * DD + d] = o2;
        o1 += g_t1[(bh * NT + t) * DD + d];
        o2 += g_t2[(bh * NT + t) * DD + d];
        hm += g_hp[(bh * NT + t) * DD + d];
    }
    g_off1[(bh * (NT + 1) + NT) * DD + d] = o1;
    g_off2[(bh * (NT + 1) + NT) * DD + d] = o2;
    g_hmean[bh * DD + d] = hm * (1.f / (float)NN);

    __shared__ float so1[NT + 1], so2[NT + 1];
    int base = bh * (NN + 1);
    if (d == 0) {
        float a1 = 0.f, a2 = 0.f;
#pragma unroll
        for (int t = 0; t < NT; t++) {
            so1[t] = a1; so2[t] = a2;
            a1 += g_s1[base + t * TILE + TILE];
            a2 += g_s2[base + t * TILE + TILE];
        }
        so1[NT] = a1; so2[NT] = a2;
        g_s1[base] = 0.f; g_s2[base] = 0.f;
    }
    __syncthreads();
    for (int k = d + 1; k <= NN; k += DD) {
        int t = (k - 1) >> TSH;
        g_s1[base + k] += so1[t];
        g_s2[base + k] += so2[t];
    }
}

// ---------------- kernel 5: per-row combine + residual + LayerNorm ------------
__global__ __launch_bounds__(128)
void k_final(const float* __restrict__ x, const int* __restrict__ mask,
             const float* __restrict__ gamma, const float* __restrict__ beta,
             float* __restrict__ out)
{
    int row  = blockIdx.x;
    int b    = row >> 10;
    int tid  = threadIdx.x;
    int warp = tid >> 5;
    int lane = tid & 31;
    __shared__ float yv[FF];
    __shared__ float red[8];

    int nv = g_nvalid[b];
    bool uni = (mask[row] == 0) || (nv == 0);
    int hh = warp;
    int bh = b * 4 + hh;

    float4 xr = *reinterpret_cast<const float4*>(&x[(size_t)row * FF + hh * DD + lane * 4]);
    float4 y;
    if (uni) {
        float4 hm = *reinterpret_cast<const float4*>(&g_hmean[bh * DD + lane * 4]);
        y.x = hm.x + xr.x; y.y = hm.y + xr.y; y.z = hm.z + xr.z; y.w = hm.w + xr.w;
    } else {
        float ei = g_esrc[row * 4 + hh];
        float tt = -ei;
        const float* keys = g_key + bh * NN;
        int lo = 0, hi = nv;
        while (lo < hi) {
            int mid = (lo + hi) >> 1;
            if (keys[mid] <= tt) lo = mid + 1; else hi = mid;
        }
        int k0 = lo;
        int t0 = k0 >> TSH, m0 = k0 & (TILE - 1);
        int tn = nv >> TSH, mn = nv & (TILE - 1);

        float w1 = __expf(0.2f * ei);
        float w2 = __expf(ei);
        float den = w1 * g_s1[bh * (NN + 1) + k0]
                  + w2 * (g_s2[bh * (NN + 1) + nv] - g_s2[bh * (NN + 1) + k0]);
        float inv = 1.0f / den;

        const float4 z4 = make_float4(0.f, 0.f, 0.f, 0.f);
        size_t ob = (size_t)(bh * (NT + 1));
        float4 o1 = *reinterpret_cast<const float4*>(&g_off1[(ob + t0) * DD + lane * 4]);
        float4 o2 = *reinterpret_cast<const float4*>(&g_off2[(ob + t0) * DD + lane * 4]);
        float4 on = *reinterpret_cast<const float4*>(&g_off2[(ob + tn) * DD + lane * 4]);
        float4 l1 = m0 ? *reinterpret_cast<const float4*>(
                        &g_p1[((size_t)bh * NN + k0 - 1) * DD + lane * 4]) : z4;
        float4 l2 = m0 ? *reinterpret_cast<const float4*>(
                        &g_p2[((size_t)bh * NN + k0 - 1) * DD + lane * 4]) : z4;
        float4 ln = mn ? *reinterpret_cast<const float4*>(
                        &g_p2[((size_t)bh * NN + nv - 1) * DD + lane * 4]) : z4;

        float P1x = o1.x + l1.x, P1y = o1.y + l1.y, P1z = o1.z + l1.z, P1w = o1.w + l1.w;
        float Pax = o2.x + l2.x, Pay = o2.y + l2.y, Paz = o2.z + l2.z, Paw = o2.w + l2.w;
        float Pbx = on.x + ln.x, Pby = on.y + ln.y, Pbz = on.z + ln.z, Pbw = on.w + ln.w;

        y.x = (w1 * P1x + w2 * (Pbx - Pax)) * inv + xr.x;
        y.y = (w1 * P1y + w2 * (Pby - Pay)) * inv + xr.y;
        y.z = (w1 * P1z + w2 * (Pbz - Paz)) * inv + xr.z;
        y.w = (w1 * P1w + w2 * (Pbw - Paw)) * inv + xr.w;
    }
    *reinterpret_cast<float4*>(&yv[hh * DD + lane * 4]) = y;
    __syncthreads();

    float s = 0.f;
#pragma unroll
    for (int u = 0; u < 4; u++) s += yv[tid + u * 128];
#pragma unroll
    for (int o = 16; o > 0; o >>= 1) s += __shfl_xor_sync(0xffffffffu, s, o);
    if (lane == 0) red[warp] = s;
    __syncthreads();
    float mu = (red[0] + red[1] + red[2] + red[3]) * (1.0f / (float)FF);

    float q = 0.f;
#pragma unroll
    for (int u = 0; u < 4; u++) {
        float dlt = yv[tid + u * 128] - mu;
        q += dlt * dlt;
    }
#pragma unroll
    for (int o = 16; o > 0; o >>= 1) q += __shfl_xor_sync(0xffffffffu, q, o);
    if (lane == 0) red[4 + warp] = q;
    __syncthreads();
    float var = (red[4] + red[5] + red[6] + red[7]) * (1.0f / (float)FF);
    float rs = rsqrtf(var + LN_EPS);

#pragma unroll
    for (int u = 0; u < 4; u++) {
        int c = tid + u * 128;
        out[(size_t)row * FF + c] = (yv[c] - mu) * rs * gamma[c] + beta[c];
    }
}

// ---------------- launch ------------------------------------------------------
extern "C" void kernel_launch(void* const* d_in, const int* in_sizes, int n_in,
                              void* d_out, int out_size)
{
    const float* x     = (const float*)d_in[0];
    const int*   mask  = (const int*)  d_in[1];
    const float* W     = (const float*)d_in[2];
    const float* a_src = (const float*)d_in[3];
    const float* a_dst = (const float*)d_in[4];
    const float* gamma = (const float*)d_in[5];
    const float* beta  = (const float*)d_in[6];
    float* out = (float*)d_out;

    static int smem_set = 0;
    if (!smem_set) {
        cudaFuncSetAttribute(k_gemm_mma,
                             cudaFuncAttributeMaxDynamicSharedMemorySize, SMEM_GEMM);
        smem_set = 1;
    }

    k_convA<<<(ROWS * FF) / (256 * 8), 256>>>(x);                    // launch 1
    k_convB<<<dim3(FF / 64, FF / 64), 256>>>(W);                     // launch 2
    k_nv   <<<BB, 1024>>>(mask);                                     // launch 3
    k_gemm_mma<<<dim3(FF / 128, ROWS / 128), 256, SMEM_GEMM>>>(a_src, a_dst); // launch 4 (profiled)
    k_sort <<<BH, NN>>>(mask);
    k_scanA<<<dim3(NT, BH), DD>>>();
    k_scanB<<<BH, DD>>>();
    k_final<<<ROWS, 128>>>(x, mask, gamma, beta, out);
}